// round 3
// baseline (speedup 1.0000x reference)
#include <cuda_runtime.h>
#include <math.h>

#define NODE   5
#define FML    64
#define F0C    256
#define F1C    256
#define FOC    256
#define TSTEPS 128
#define BTOT   8192
#define MROWS  64
#define NCTA   (BTOT / MROWS)   // 128
#define NTHR   256
#define BN_EPS 1e-5f

// Scratch (static device arrays: allocation-free)
__device__ float g_h[BTOT * FOC];       // post-ReLU head activations (B,256)
__device__ float g_stats[2 * FOC];      // [0:256) sum, [256:512) sumsq

__constant__ int c_par[NODE][2] = {{3,4},{0,4},{0,1},{1,2},{2,3}};

struct SmemLayout {
    float state[NODE][MROWS][FML];      // 81920 B
    float snew[NODE - 1][MROWS][FML];   // 65536 B
    float h1[32][F0C];                  // 32768 B
    float h2[32][F1C];                  // 32768 B
    float xs[NODE][MROWS];              //  1280 B
    float red[2][FOC];                  //  2048 B
};                                      // total 216320 B

// C[4 rows][8 cols] += A[4 rows][K] * B[K][8 cols]; A rows in smem, B in gmem(L2/L1)
__device__ __forceinline__ void mac8(float (&acc)[4][8],
    const float* __restrict__ a0, const float* __restrict__ a1,
    const float* __restrict__ a2, const float* __restrict__ a3,
    const float* __restrict__ B, int ldb, int K)
{
#pragma unroll 2
    for (int k4 = 0; k4 < (K >> 2); ++k4) {
        float a[4][4];
        {
            float4 t;
            t = *reinterpret_cast<const float4*>(a0 + 4 * k4);
            a[0][0] = t.x; a[0][1] = t.y; a[0][2] = t.z; a[0][3] = t.w;
            t = *reinterpret_cast<const float4*>(a1 + 4 * k4);
            a[1][0] = t.x; a[1][1] = t.y; a[1][2] = t.z; a[1][3] = t.w;
            t = *reinterpret_cast<const float4*>(a2 + 4 * k4);
            a[2][0] = t.x; a[2][1] = t.y; a[2][2] = t.z; a[2][3] = t.w;
            t = *reinterpret_cast<const float4*>(a3 + 4 * k4);
            a[3][0] = t.x; a[3][1] = t.y; a[3][2] = t.z; a[3][3] = t.w;
        }
        const float* Bk = B + (size_t)(4 * k4) * ldb;
#pragma unroll
        for (int kk = 0; kk < 4; ++kk) {
            const float4 bq0 = *reinterpret_cast<const float4*>(Bk);
            const float4 bq1 = *reinterpret_cast<const float4*>(Bk + 4);
            Bk += ldb;
#pragma unroll
            for (int i = 0; i < 4; ++i) {
                acc[i][0] = fmaf(a[i][kk], bq0.x, acc[i][0]);
                acc[i][1] = fmaf(a[i][kk], bq0.y, acc[i][1]);
                acc[i][2] = fmaf(a[i][kk], bq0.z, acc[i][2]);
                acc[i][3] = fmaf(a[i][kk], bq0.w, acc[i][3]);
                acc[i][4] = fmaf(a[i][kk], bq1.x, acc[i][4]);
                acc[i][5] = fmaf(a[i][kk], bq1.y, acc[i][5]);
                acc[i][6] = fmaf(a[i][kk], bq1.z, acc[i][6]);
                acc[i][7] = fmaf(a[i][kk], bq1.w, acc[i][7]);
            }
        }
    }
}

// C[4][2] += A[4][K] * B[K][2]
__device__ __forceinline__ void mac2(float (&acc)[4][2],
    const float* __restrict__ a0, const float* __restrict__ a1,
    const float* __restrict__ a2, const float* __restrict__ a3,
    const float* __restrict__ B, int ldb, int K)
{
#pragma unroll 2
    for (int k4 = 0; k4 < (K >> 2); ++k4) {
        float a[4][4];
        {
            float4 t;
            t = *reinterpret_cast<const float4*>(a0 + 4 * k4);
            a[0][0] = t.x; a[0][1] = t.y; a[0][2] = t.z; a[0][3] = t.w;
            t = *reinterpret_cast<const float4*>(a1 + 4 * k4);
            a[1][0] = t.x; a[1][1] = t.y; a[1][2] = t.z; a[1][3] = t.w;
            t = *reinterpret_cast<const float4*>(a2 + 4 * k4);
            a[2][0] = t.x; a[2][1] = t.y; a[2][2] = t.z; a[2][3] = t.w;
            t = *reinterpret_cast<const float4*>(a3 + 4 * k4);
            a[3][0] = t.x; a[3][1] = t.y; a[3][2] = t.z; a[3][3] = t.w;
        }
        const float* Bk = B + (size_t)(4 * k4) * ldb;
#pragma unroll
        for (int kk = 0; kk < 4; ++kk) {
            const float2 bq = *reinterpret_cast<const float2*>(Bk);
            Bk += ldb;
#pragma unroll
            for (int i = 0; i < 4; ++i) {
                acc[i][0] = fmaf(a[i][kk], bq.x, acc[i][0]);
                acc[i][1] = fmaf(a[i][kk], bq.y, acc[i][1]);
            }
        }
    }
}

__global__ void zero_stats_kernel()
{
    int i = blockIdx.x * blockDim.x + threadIdx.x;
    if (i < 2 * FOC) g_stats[i] = 0.0f;
}

__global__ __launch_bounds__(NTHR)
void rnn_kernel(const float* __restrict__ x,
                const float* __restrict__ W1, const float* __restrict__ b1,
                const float* __restrict__ W2, const float* __restrict__ b2,
                const float* __restrict__ W3, const float* __restrict__ b3,
                const float* __restrict__ Wo1, const float* __restrict__ bo1)
{
    extern __shared__ char smem_raw[];
    SmemLayout& S = *reinterpret_cast<SmemLayout*>(smem_raw);
    const int tid = threadIdx.x;
    const int tx  = tid & 31;   // column group
    const int ty  = tid >> 5;   // row group (0..7)
    const int b0  = blockIdx.x * MROWS;

    // init state = 0, reduction buffers = 0
    {
        float* st = &S.state[0][0][0];
        for (int i = tid; i < NODE * MROWS * FML; i += NTHR) st[i] = 0.0f;
        float* rd = &S.red[0][0];
        for (int i = tid; i < 2 * FOC; i += NTHR) rd[i] = 0.0f;
    }
    __syncthreads();

    for (int t = 0; t < TSTEPS; ++t) {
        // stage x_t for this CTA's rows: x[b,0,n,t] at b*640 + n*128 + t
        for (int i = tid; i < NODE * MROWS; i += NTHR) {
            int n = i >> 6, r = i & 63;
            S.xs[n][r] = x[(size_t)(b0 + r) * (NODE * TSTEPS) + n * TSTEPS + t];
        }
        __syncthreads();

        for (int n = 0; n < NODE; ++n) {
            const int p0 = c_par[n][0], p1 = c_par[n][1];
            const float* W1n = W1 + (size_t)n * (2 + 2 * FML) * F0C;
            const float* W2n = W2 + (size_t)n * F0C * F1C;
            const float* W3n = W3 + (size_t)n * F1C * FML;

            for (int hh = 0; hh < 2; ++hh) {
                const int mr = hh * 32 + ty * 4;   // CTA row base for this thread
                const int lr = ty * 4;             // local row within 32-row half
                const int c0 = tx * 8;

                // ---------- Layer 1: inp(130) -> 256, ReLU ----------
                float acc[4][8];
                {
                    const float4 bb0 = *reinterpret_cast<const float4*>(b1 + n * F0C + c0);
                    const float4 bb1 = *reinterpret_cast<const float4*>(b1 + n * F0C + c0 + 4);
                    const float4 wA0 = *reinterpret_cast<const float4*>(W1n + c0);
                    const float4 wA1 = *reinterpret_cast<const float4*>(W1n + c0 + 4);
                    const float4 wB0 = *reinterpret_cast<const float4*>(W1n + F0C + c0);
                    const float4 wB1 = *reinterpret_cast<const float4*>(W1n + F0C + c0 + 4);
#pragma unroll
                    for (int i = 0; i < 4; ++i) {
                        const float xa = S.xs[p0][mr + i];
                        const float xb = S.xs[p1][mr + i];
                        acc[i][0] = fmaf(xa, wA0.x, fmaf(xb, wB0.x, bb0.x));
                        acc[i][1] = fmaf(xa, wA0.y, fmaf(xb, wB0.y, bb0.y));
                        acc[i][2] = fmaf(xa, wA0.z, fmaf(xb, wB0.z, bb0.z));
                        acc[i][3] = fmaf(xa, wA0.w, fmaf(xb, wB0.w, bb0.w));
                        acc[i][4] = fmaf(xa, wA1.x, fmaf(xb, wB1.x, bb1.x));
                        acc[i][5] = fmaf(xa, wA1.y, fmaf(xb, wB1.y, bb1.y));
                        acc[i][6] = fmaf(xa, wA1.z, fmaf(xb, wB1.z, bb1.z));
                        acc[i][7] = fmaf(xa, wA1.w, fmaf(xb, wB1.w, bb1.w));
                    }
                }
                mac8(acc, S.state[p0][mr + 0], S.state[p0][mr + 1],
                          S.state[p0][mr + 2], S.state[p0][mr + 3],
                     W1n + 2 * F0C + c0, F0C, FML);
                mac8(acc, S.state[p1][mr + 0], S.state[p1][mr + 1],
                          S.state[p1][mr + 2], S.state[p1][mr + 3],
                     W1n + (size_t)(2 + FML) * F0C + c0, F0C, FML);
#pragma unroll
                for (int i = 0; i < 4; ++i) {
                    float4 v0 = make_float4(fmaxf(acc[i][0], 0.f), fmaxf(acc[i][1], 0.f),
                                            fmaxf(acc[i][2], 0.f), fmaxf(acc[i][3], 0.f));
                    float4 v1 = make_float4(fmaxf(acc[i][4], 0.f), fmaxf(acc[i][5], 0.f),
                                            fmaxf(acc[i][6], 0.f), fmaxf(acc[i][7], 0.f));
                    *reinterpret_cast<float4*>(&S.h1[lr + i][c0])     = v0;
                    *reinterpret_cast<float4*>(&S.h1[lr + i][c0 + 4]) = v1;
                }
                __syncthreads();

                // ---------- Layer 2: 256 -> 256, ReLU ----------
                {
                    const float4 bb0 = *reinterpret_cast<const float4*>(b2 + n * F1C + c0);
                    const float4 bb1 = *reinterpret_cast<const float4*>(b2 + n * F1C + c0 + 4);
#pragma unroll
                    for (int i = 0; i < 4; ++i) {
                        acc[i][0] = bb0.x; acc[i][1] = bb0.y; acc[i][2] = bb0.z; acc[i][3] = bb0.w;
                        acc[i][4] = bb1.x; acc[i][5] = bb1.y; acc[i][6] = bb1.z; acc[i][7] = bb1.w;
                    }
                }
                mac8(acc, S.h1[lr + 0], S.h1[lr + 1], S.h1[lr + 2], S.h1[lr + 3],
                     W2n + c0, F1C, F0C);
#pragma unroll
                for (int i = 0; i < 4; ++i) {
                    float4 v0 = make_float4(fmaxf(acc[i][0], 0.f), fmaxf(acc[i][1], 0.f),
                                            fmaxf(acc[i][2], 0.f), fmaxf(acc[i][3], 0.f));
                    float4 v1 = make_float4(fmaxf(acc[i][4], 0.f), fmaxf(acc[i][5], 0.f),
                                            fmaxf(acc[i][6], 0.f), fmaxf(acc[i][7], 0.f));
                    *reinterpret_cast<float4*>(&S.h2[lr + i][c0])     = v0;
                    *reinterpret_cast<float4*>(&S.h2[lr + i][c0 + 4]) = v1;
                }
                __syncthreads();

                // ---------- Layer 3: 256 -> 64, tanh -> new state ----------
                {
                    const int c3 = tx * 2;
                    float a3[4][2];
                    const float2 bb = *reinterpret_cast<const float2*>(b3 + n * FML + c3);
#pragma unroll
                    for (int i = 0; i < 4; ++i) { a3[i][0] = bb.x; a3[i][1] = bb.y; }
                    mac2(a3, S.h2[lr + 0], S.h2[lr + 1], S.h2[lr + 2], S.h2[lr + 3],
                         W3n + c3, FML, F1C);
                    float* dst = (n < 4) ? &S.snew[n][0][0] : &S.state[4][0][0];
#pragma unroll
                    for (int i = 0; i < 4; ++i) {
                        dst[(size_t)(mr + i) * FML + c3]     = tanhf(a3[i][0]);
                        dst[(size_t)(mr + i) * FML + c3 + 1] = tanhf(a3[i][1]);
                    }
                }
                __syncthreads();
            }
        }

        // commit new states for nodes 0..3 (node 4 was written in place)
        {
            float4* d = reinterpret_cast<float4*>(&S.state[0][0][0]);
            const float4* s = reinterpret_cast<const float4*>(&S.snew[0][0][0]);
            for (int i = tid; i < (NODE - 1) * MROWS * FML / 4; i += NTHR) d[i] = s[i];
        }
        __syncthreads();
    }

    // ---------- Head GEMM: feat(325) @ Wo1 -> ReLU -> g_h, partial BN sums ----------
    for (int hh = 0; hh < 2; ++hh) {
        const int mr = hh * 32 + ty * 4;
        const int c0 = tx * 8;
        float acc[4][8];
        {
            const float4 bb0 = *reinterpret_cast<const float4*>(bo1 + c0);
            const float4 bb1 = *reinterpret_cast<const float4*>(bo1 + c0 + 4);
#pragma unroll
            for (int i = 0; i < 4; ++i) {
                acc[i][0] = bb0.x; acc[i][1] = bb0.y; acc[i][2] = bb0.z; acc[i][3] = bb0.w;
                acc[i][4] = bb1.x; acc[i][5] = bb1.y; acc[i][6] = bb1.z; acc[i][7] = bb1.w;
            }
        }
#pragma unroll
        for (int n = 0; n < NODE; ++n) {   // x part of feat (rows 0..4 of Wo1)
            const float4 w0 = *reinterpret_cast<const float4*>(Wo1 + n * FOC + c0);
            const float4 w1 = *reinterpret_cast<const float4*>(Wo1 + n * FOC + c0 + 4);
#pragma unroll
            for (int i = 0; i < 4; ++i) {
                const float xv = S.xs[n][mr + i];   // xs holds t = T-1
                acc[i][0] = fmaf(xv, w0.x, acc[i][0]);
                acc[i][1] = fmaf(xv, w0.y, acc[i][1]);
                acc[i][2] = fmaf(xv, w0.z, acc[i][2]);
                acc[i][3] = fmaf(xv, w0.w, acc[i][3]);
                acc[i][4] = fmaf(xv, w1.x, acc[i][4]);
                acc[i][5] = fmaf(xv, w1.y, acc[i][5]);
                acc[i][6] = fmaf(xv, w1.z, acc[i][6]);
                acc[i][7] = fmaf(xv, w1.w, acc[i][7]);
            }
        }
        for (int n = 0; n < NODE; ++n) {   // state part (rows 5 + n*64 + f)
            mac8(acc, S.state[n][mr + 0], S.state[n][mr + 1],
                      S.state[n][mr + 2], S.state[n][mr + 3],
                 Wo1 + (size_t)(NODE + n * FML) * FOC + c0, FOC, FML);
        }
        float cs[8] = {0, 0, 0, 0, 0, 0, 0, 0};
        float cq[8] = {0, 0, 0, 0, 0, 0, 0, 0};
#pragma unroll
        for (int i = 0; i < 4; ++i) {
            float v[8];
#pragma unroll
            for (int j = 0; j < 8; ++j) {
                v[j] = fmaxf(acc[i][j], 0.f);
                cs[j] += v[j];
                cq[j] += v[j] * v[j];
            }
            *reinterpret_cast<float4*>(&g_h[(size_t)(b0 + mr + i) * FOC + c0]) =
                make_float4(v[0], v[1], v[2], v[3]);
            *reinterpret_cast<float4*>(&g_h[(size_t)(b0 + mr + i) * FOC + c0 + 4]) =
                make_float4(v[4], v[5], v[6], v[7]);
        }
#pragma unroll
        for (int j = 0; j < 8; ++j) {
            atomicAdd(&S.red[0][c0 + j], cs[j]);
            atomicAdd(&S.red[1][c0 + j], cq[j]);
        }
    }
    __syncthreads();
    if (tid < FOC) {
        atomicAdd(&g_stats[tid],       S.red[0][tid]);
        atomicAdd(&g_stats[FOC + tid], S.red[1][tid]);
    }
}

// ---------- BN + logits + softmax ----------
__global__ __launch_bounds__(256)
void head_kernel(const float* __restrict__ gamma, const float* __restrict__ beta,
                 const float* __restrict__ Wo2, const float* __restrict__ bo2,
                 float* __restrict__ out)
{
    __shared__ float s_scale[FOC];
    __shared__ float s_shift[FOC];
    __shared__ float s_w[FOC * 7];
    __shared__ float s_b[7];
    const int tid = threadIdx.x;

    if (tid < FOC) {
        const float inv = 1.0f / (float)BTOT;
        float mu  = g_stats[tid] * inv;
        float var = g_stats[FOC + tid] * inv - mu * mu;
        float sc  = gamma[tid] * rsqrtf(var + BN_EPS);
        s_scale[tid] = sc;
        s_shift[tid] = beta[tid] - mu * sc;
    }
    for (int i = tid; i < FOC * 7; i += 256) s_w[i] = Wo2[i];
    if (tid < 7) s_b[tid] = bo2[tid];
    __syncthreads();

    const int lane = tid & 31;
    const int warp = tid >> 5;
    const int row  = blockIdx.x * 8 + warp;

    float l[7] = {0, 0, 0, 0, 0, 0, 0};
#pragma unroll
    for (int ii = 0; ii < 8; ++ii) {
        const int c = lane + 32 * ii;
        const float v  = g_h[(size_t)row * FOC + c];
        const float hn = fmaf(v, s_scale[c], s_shift[c]);
#pragma unroll
        for (int j = 0; j < 7; ++j) l[j] = fmaf(hn, s_w[c * 7 + j], l[j]);
    }
#pragma unroll
    for (int off = 16; off > 0; off >>= 1) {
#pragma unroll
        for (int j = 0; j < 7; ++j) l[j] += __shfl_xor_sync(0xFFFFFFFFu, l[j], off);
    }
    if (lane == 0) {
        float m = -1e30f;
#pragma unroll
        for (int j = 0; j < 7; ++j) { l[j] += s_b[j]; m = fmaxf(m, l[j]); }
        float e[7], sum = 0.f;
#pragma unroll
        for (int j = 0; j < 7; ++j) { e[j] = expf(l[j] - m); sum += e[j]; }
        const float r = 1.0f / sum;
#pragma unroll
        for (int j = 0; j < 7; ++j) out[(size_t)row * 7 + j] = e[j] * r;
    }
}

extern "C" void kernel_launch(void* const* d_in, const int* in_sizes, int n_in,
                              void* d_out, int out_size)
{
    (void)in_sizes; (void)n_in; (void)out_size;
    const float* x    = (const float*)d_in[0];
    const float* W1   = (const float*)d_in[1];
    const float* b1   = (const float*)d_in[2];
    const float* W2   = (const float*)d_in[3];
    const float* b2   = (const float*)d_in[4];
    const float* W3   = (const float*)d_in[5];
    const float* b3   = (const float*)d_in[6];
    const float* Wo1  = (const float*)d_in[7];
    const float* bo1  = (const float*)d_in[8];
    const float* gam  = (const float*)d_in[9];
    const float* bet  = (const float*)d_in[10];
    const float* Wo2  = (const float*)d_in[11];
    const float* bo2  = (const float*)d_in[12];
    float* out = (float*)d_out;

    cudaFuncSetAttribute(rnn_kernel, cudaFuncAttributeMaxDynamicSharedMemorySize,
                         (int)sizeof(SmemLayout));

    zero_stats_kernel<<<2, 256>>>();
    rnn_kernel<<<NCTA, NTHR, sizeof(SmemLayout)>>>(x, W1, b1, W2, b2, W3, b3, Wo1, bo1);
    head_kernel<<<BTOT / 8, 256>>>(gam, bet, Wo2, bo2, out);
}

// round 5
// speedup vs baseline: 1.0380x; 1.0380x over previous
#include <cuda_runtime.h>
#include <math.h>

#define NODE   5
#define FML    64
#define F0C    256
#define F1C    256
#define FOC    256
#define TSTEPS 128
#define BTOT   8192
#define MROWS  64
#define NCTA   (BTOT / MROWS)   // 128
#define NTHR   256
#define BN_EPS 1e-5f

// Scratch (static device arrays: allocation-free)
__device__ float g_h[BTOT * FOC];       // post-ReLU head activations (B,256)
__device__ float g_stats[2 * FOC];      // [0:256) sum, [256:512) sumsq

__constant__ int c_par[NODE][2] = {{3,4},{0,4},{0,1},{1,2},{2,3}};

struct SmemLayout {
    float state[NODE][MROWS][FML];      // 81920 B
    float snew[NODE - 1][MROWS][FML];   // 65536 B
    float h1[32][F0C];                  // 32768 B
    float h2[32][F1C];                  // 32768 B
    float xs[NODE][MROWS];              //  1280 B
    float red[2][FOC];                  //  2048 B
};                                      // total 216320 B

typedef unsigned long long u64;

// duplicate a float into both halves of a packed f32x2 register
__device__ __forceinline__ u64 dupf(float v) {
    u64 r;
    asm("mov.b64 %0, {%1, %1};" : "=l"(r) : "r"(__float_as_uint(v)));
    return r;
}

// packed dual-FMA: d.lo += a.lo*b.lo ; d.hi += a.hi*b.hi  (FFMA2)
__device__ __forceinline__ void ffma2(u64& d, u64 a, u64 b) {
    asm("fma.rn.f32x2 %0, %1, %2, %0;" : "+l"(d) : "l"(a), "l"(b));
}

// C[4 rows][8 cols(packed as 4 pairs)] += A[4 rows][K] * B[K][8 cols]
// A rows in smem (broadcast loads), B in gmem (L2). Loads batched up front.
__device__ __forceinline__ void mac8p(u64 (&acc)[4][4],
    const float* __restrict__ a0, const float* __restrict__ a1,
    const float* __restrict__ a2, const float* __restrict__ a3,
    const float* __restrict__ B, int ldb, int K)
{
#pragma unroll 2
    for (int k4 = 0; k4 < (K >> 2); ++k4) {
        const float4 ta = *reinterpret_cast<const float4*>(a0 + 4 * k4);
        const float4 tb = *reinterpret_cast<const float4*>(a1 + 4 * k4);
        const float4 tc = *reinterpret_cast<const float4*>(a2 + 4 * k4);
        const float4 td = *reinterpret_cast<const float4*>(a3 + 4 * k4);
        const float* Bk = B + (size_t)(4 * k4) * ldb;
        const ulonglong2 q0 = *reinterpret_cast<const ulonglong2*>(Bk);
        const ulonglong2 q1 = *reinterpret_cast<const ulonglong2*>(Bk + 4);
        const ulonglong2 q2 = *reinterpret_cast<const ulonglong2*>(Bk + ldb);
        const ulonglong2 q3 = *reinterpret_cast<const ulonglong2*>(Bk + ldb + 4);
        const ulonglong2 q4 = *reinterpret_cast<const ulonglong2*>(Bk + 2 * ldb);
        const ulonglong2 q5 = *reinterpret_cast<const ulonglong2*>(Bk + 2 * ldb + 4);
        const ulonglong2 q6 = *reinterpret_cast<const ulonglong2*>(Bk + 3 * ldb);
        const ulonglong2 q7 = *reinterpret_cast<const ulonglong2*>(Bk + 3 * ldb + 4);
        u64 ap[4];
        // kk = 0
        ap[0] = dupf(ta.x); ap[1] = dupf(tb.x); ap[2] = dupf(tc.x); ap[3] = dupf(td.x);
#pragma unroll
        for (int i = 0; i < 4; ++i) {
            ffma2(acc[i][0], ap[i], q0.x); ffma2(acc[i][1], ap[i], q0.y);
            ffma2(acc[i][2], ap[i], q1.x); ffma2(acc[i][3], ap[i], q1.y);
        }
        // kk = 1
        ap[0] = dupf(ta.y); ap[1] = dupf(tb.y); ap[2] = dupf(tc.y); ap[3] = dupf(td.y);
#pragma unroll
        for (int i = 0; i < 4; ++i) {
            ffma2(acc[i][0], ap[i], q2.x); ffma2(acc[i][1], ap[i], q2.y);
            ffma2(acc[i][2], ap[i], q3.x); ffma2(acc[i][3], ap[i], q3.y);
        }
        // kk = 2
        ap[0] = dupf(ta.z); ap[1] = dupf(tb.z); ap[2] = dupf(tc.z); ap[3] = dupf(td.z);
#pragma unroll
        for (int i = 0; i < 4; ++i) {
            ffma2(acc[i][0], ap[i], q4.x); ffma2(acc[i][1], ap[i], q4.y);
            ffma2(acc[i][2], ap[i], q5.x); ffma2(acc[i][3], ap[i], q5.y);
        }
        // kk = 3
        ap[0] = dupf(ta.w); ap[1] = dupf(tb.w); ap[2] = dupf(tc.w); ap[3] = dupf(td.w);
#pragma unroll
        for (int i = 0; i < 4; ++i) {
            ffma2(acc[i][0], ap[i], q6.x); ffma2(acc[i][1], ap[i], q6.y);
            ffma2(acc[i][2], ap[i], q7.x); ffma2(acc[i][3], ap[i], q7.y);
        }
    }
}

// C[4 rows][2 cols packed] += A[4 rows][K] * B[K][2 cols]
__device__ __forceinline__ void mac2p(u64 (&acc)[4],
    const float* __restrict__ a0, const float* __restrict__ a1,
    const float* __restrict__ a2, const float* __restrict__ a3,
    const float* __restrict__ B, int ldb, int K)
{
#pragma unroll 2
    for (int k4 = 0; k4 < (K >> 2); ++k4) {
        const float4 ta = *reinterpret_cast<const float4*>(a0 + 4 * k4);
        const float4 tb = *reinterpret_cast<const float4*>(a1 + 4 * k4);
        const float4 tc = *reinterpret_cast<const float4*>(a2 + 4 * k4);
        const float4 td = *reinterpret_cast<const float4*>(a3 + 4 * k4);
        const float* Bk = B + (size_t)(4 * k4) * ldb;
        const u64 w0 = *reinterpret_cast<const u64*>(Bk);
        const u64 w1 = *reinterpret_cast<const u64*>(Bk + ldb);
        const u64 w2 = *reinterpret_cast<const u64*>(Bk + 2 * ldb);
        const u64 w3 = *reinterpret_cast<const u64*>(Bk + 3 * ldb);
        ffma2(acc[0], dupf(ta.x), w0); ffma2(acc[1], dupf(tb.x), w0);
        ffma2(acc[2], dupf(tc.x), w0); ffma2(acc[3], dupf(td.x), w0);
        ffma2(acc[0], dupf(ta.y), w1); ffma2(acc[1], dupf(tb.y), w1);
        ffma2(acc[2], dupf(tc.y), w1); ffma2(acc[3], dupf(td.y), w1);
        ffma2(acc[0], dupf(ta.z), w2); ffma2(acc[1], dupf(tb.z), w2);
        ffma2(acc[2], dupf(tc.z), w2); ffma2(acc[3], dupf(td.z), w2);
        ffma2(acc[0], dupf(ta.w), w3); ffma2(acc[1], dupf(tb.w), w3);
        ffma2(acc[2], dupf(tc.w), w3); ffma2(acc[3], dupf(td.w), w3);
    }
}

__global__ void zero_stats_kernel()
{
    int i = blockIdx.x * blockDim.x + threadIdx.x;
    if (i < 2 * FOC) g_stats[i] = 0.0f;
}

__global__ __launch_bounds__(NTHR)
void rnn_kernel(const float* __restrict__ x,
                const float* __restrict__ W1, const float* __restrict__ b1,
                const float* __restrict__ W2, const float* __restrict__ b2,
                const float* __restrict__ W3, const float* __restrict__ b3,
                const float* __restrict__ Wo1, const float* __restrict__ bo1)
{
    extern __shared__ char smem_raw[];
    SmemLayout& S = *reinterpret_cast<SmemLayout*>(smem_raw);
    const int tid = threadIdx.x;
    const int tx  = tid & 31;   // lane / column group
    const int ty  = tid >> 5;   // warp / row group (0..7)
    const int b0  = blockIdx.x * MROWS;

    // init state = 0, reduction buffers = 0
    {
        float* st = &S.state[0][0][0];
        for (int i = tid; i < NODE * MROWS * FML; i += NTHR) st[i] = 0.0f;
        float* rd = &S.red[0][0];
        for (int i = tid; i < 2 * FOC; i += NTHR) rd[i] = 0.0f;
    }
    __syncthreads();   // the ONLY CTA barrier before the head

    // Every warp owns batch rows {ty*4..ty*4+3} and {32+ty*4..32+ty*4+3} of
    // state/snew/h1/h2/xs — the whole recurrence is warp-private, so the
    // timestep loop uses only __syncwarp().
    for (int t = 0; t < TSTEPS; ++t) {
        // per-warp staging of x_t for this warp's 8 rows, all 5 nodes
        for (int i = tx; i < NODE * 8; i += 32) {
            const int nn = i >> 3, r8 = i & 7;
            const int r = ((r8 & 4) ? 32 : 0) + ty * 4 + (r8 & 3);
            S.xs[nn][r] = x[(size_t)(b0 + r) * (NODE * TSTEPS) + nn * TSTEPS + t];
        }
        __syncwarp();

        for (int n = 0; n < NODE; ++n) {
            const int p0 = c_par[n][0], p1 = c_par[n][1];
            const float* W1n = W1 + (size_t)n * (2 + 2 * FML) * F0C;
            const float* W2n = W2 + (size_t)n * F0C * F1C;
            const float* W3n = W3 + (size_t)n * F1C * FML;

            for (int hh = 0; hh < 2; ++hh) {
                const int mr = hh * 32 + ty * 4;   // CTA row base for this thread
                const int lr = ty * 4;             // local row within 32-row half
                const int c0 = tx * 8;

                // ---------- Layer 1: inp(130) -> 256, ReLU ----------
                u64 acc[4][4];
                {
                    const ulonglong2 bb0 = *reinterpret_cast<const ulonglong2*>(b1 + n * F0C + c0);
                    const ulonglong2 bb1 = *reinterpret_cast<const ulonglong2*>(b1 + n * F0C + c0 + 4);
                    const ulonglong2 wa0 = *reinterpret_cast<const ulonglong2*>(W1n + c0);
                    const ulonglong2 wa1 = *reinterpret_cast<const ulonglong2*>(W1n + c0 + 4);
                    const ulonglong2 wb0 = *reinterpret_cast<const ulonglong2*>(W1n + F0C + c0);
                    const ulonglong2 wb1 = *reinterpret_cast<const ulonglong2*>(W1n + F0C + c0 + 4);
#pragma unroll
                    for (int i = 0; i < 4; ++i) {
                        const u64 xa = dupf(S.xs[p0][mr + i]);
                        const u64 xb = dupf(S.xs[p1][mr + i]);
                        acc[i][0] = bb0.x; acc[i][1] = bb0.y;
                        acc[i][2] = bb1.x; acc[i][3] = bb1.y;
                        ffma2(acc[i][0], xb, wb0.x); ffma2(acc[i][1], xb, wb0.y);
                        ffma2(acc[i][2], xb, wb1.x); ffma2(acc[i][3], xb, wb1.y);
                        ffma2(acc[i][0], xa, wa0.x); ffma2(acc[i][1], xa, wa0.y);
                        ffma2(acc[i][2], xa, wa1.x); ffma2(acc[i][3], xa, wa1.y);
                    }
                }
                mac8p(acc, S.state[p0][mr + 0], S.state[p0][mr + 1],
                           S.state[p0][mr + 2], S.state[p0][mr + 3],
                      W1n + 2 * F0C + c0, F0C, FML);
                mac8p(acc, S.state[p1][mr + 0], S.state[p1][mr + 1],
                           S.state[p1][mr + 2], S.state[p1][mr + 3],
                      W1n + (size_t)(2 + FML) * F0C + c0, F0C, FML);
#pragma unroll
                for (int i = 0; i < 4; ++i) {
                    union { u64 u[4]; float f[8]; } r;
                    r.u[0] = acc[i][0]; r.u[1] = acc[i][1];
                    r.u[2] = acc[i][2]; r.u[3] = acc[i][3];
                    *reinterpret_cast<float4*>(&S.h1[lr + i][c0]) =
                        make_float4(fmaxf(r.f[0], 0.f), fmaxf(r.f[1], 0.f),
                                    fmaxf(r.f[2], 0.f), fmaxf(r.f[3], 0.f));
                    *reinterpret_cast<float4*>(&S.h1[lr + i][c0 + 4]) =
                        make_float4(fmaxf(r.f[4], 0.f), fmaxf(r.f[5], 0.f),
                                    fmaxf(r.f[6], 0.f), fmaxf(r.f[7], 0.f));
                }
                __syncwarp();

                // ---------- Layer 2: 256 -> 256, ReLU ----------
                {
                    const ulonglong2 bb0 = *reinterpret_cast<const ulonglong2*>(b2 + n * F1C + c0);
                    const ulonglong2 bb1 = *reinterpret_cast<const ulonglong2*>(b2 + n * F1C + c0 + 4);
#pragma unroll
                    for (int i = 0; i < 4; ++i) {
                        acc[i][0] = bb0.x; acc[i][1] = bb0.y;
                        acc[i][2] = bb1.x; acc[i][3] = bb1.y;
                    }
                }
                mac8p(acc, S.h1[lr + 0], S.h1[lr + 1], S.h1[lr + 2], S.h1[lr + 3],
                      W2n + c0, F1C, F0C);
#pragma unroll
                for (int i = 0; i < 4; ++i) {
                    union { u64 u[4]; float f[8]; } r;
                    r.u[0] = acc[i][0]; r.u[1] = acc[i][1];
                    r.u[2] = acc[i][2]; r.u[3] = acc[i][3];
                    *reinterpret_cast<float4*>(&S.h2[lr + i][c0]) =
                        make_float4(fmaxf(r.f[0], 0.f), fmaxf(r.f[1], 0.f),
                                    fmaxf(r.f[2], 0.f), fmaxf(r.f[3], 0.f));
                    *reinterpret_cast<float4*>(&S.h2[lr + i][c0 + 4]) =
                        make_float4(fmaxf(r.f[4], 0.f), fmaxf(r.f[5], 0.f),
                                    fmaxf(r.f[6], 0.f), fmaxf(r.f[7], 0.f));
                }
                __syncwarp();

                // ---------- Layer 3: 256 -> 64, tanh -> new state ----------
                {
                    const int c3 = tx * 2;
                    u64 a3[4];
                    const u64 bb = *reinterpret_cast<const u64*>(b3 + n * FML + c3);
#pragma unroll
                    for (int i = 0; i < 4; ++i) a3[i] = bb;
                    mac2p(a3, S.h2[lr + 0], S.h2[lr + 1], S.h2[lr + 2], S.h2[lr + 3],
                          W3n + c3, FML, F1C);
                    float* dst = (n < 4) ? &S.snew[n][0][0] : &S.state[4][0][0];
#pragma unroll
                    for (int i = 0; i < 4; ++i) {
                        union { u64 u; float f[2]; } r;
                        r.u = a3[i];
                        dst[(size_t)(mr + i) * FML + c3]     = tanhf(r.f[0]);
                        dst[(size_t)(mr + i) * FML + c3 + 1] = tanhf(r.f[1]);
                    }
                }
                __syncwarp();
            }
        }

        // per-warp commit of snew -> state for nodes 0..3 (node 4 written in place)
        for (int i = tx; i < 512; i += 32) {           // 512 float4 per warp
            const int nn  = i >> 7;                    // node 0..3
            const int rem = i & 127;                   // 8 rows x 16 float4
            const int r8  = rem >> 4;
            const int c4  = rem & 15;
            const int r   = ((r8 & 4) ? 32 : 0) + ty * 4 + (r8 & 3);
            *(reinterpret_cast<float4*>(&S.state[nn][r][0]) + c4) =
                *(reinterpret_cast<const float4*>(&S.snew[nn][r][0]) + c4);
        }
        __syncwarp();
    }

    // ---------- Head GEMM: feat(325) @ Wo1 -> ReLU -> g_h, partial BN sums ----------
    for (int hh = 0; hh < 2; ++hh) {
        const int mr = hh * 32 + ty * 4;
        const int c0 = tx * 8;
        u64 acc[4][4];
        {
            const ulonglong2 bb0 = *reinterpret_cast<const ulonglong2*>(bo1 + c0);
            const ulonglong2 bb1 = *reinterpret_cast<const ulonglong2*>(bo1 + c0 + 4);
#pragma unroll
            for (int i = 0; i < 4; ++i) {
                acc[i][0] = bb0.x; acc[i][1] = bb0.y;
                acc[i][2] = bb1.x; acc[i][3] = bb1.y;
            }
        }
#pragma unroll
        for (int n = 0; n < NODE; ++n) {   // x part of feat (rows 0..4 of Wo1)
            const ulonglong2 w0 = *reinterpret_cast<const ulonglong2*>(Wo1 + n * FOC + c0);
            const ulonglong2 w1 = *reinterpret_cast<const ulonglong2*>(Wo1 + n * FOC + c0 + 4);
#pragma unroll
            for (int i = 0; i < 4; ++i) {
                const u64 xv = dupf(S.xs[n][mr + i]);   // xs holds t = T-1
                ffma2(acc[i][0], xv, w0.x); ffma2(acc[i][1], xv, w0.y);
                ffma2(acc[i][2], xv, w1.x); ffma2(acc[i][3], xv, w1.y);
            }
        }
        for (int n = 0; n < NODE; ++n) {   // state part (rows 5 + n*64 + f)
            mac8p(acc, S.state[n][mr + 0], S.state[n][mr + 1],
                       S.state[n][mr + 2], S.state[n][mr + 3],
                  Wo1 + (size_t)(NODE + n * FML) * FOC + c0, FOC, FML);
        }
        float cs[8] = {0, 0, 0, 0, 0, 0, 0, 0};
        float cq[8] = {0, 0, 0, 0, 0, 0, 0, 0};
#pragma unroll
        for (int i = 0; i < 4; ++i) {
            union { u64 u[4]; float f[8]; } r;
            r.u[0] = acc[i][0]; r.u[1] = acc[i][1];
            r.u[2] = acc[i][2]; r.u[3] = acc[i][3];
            float v[8];
#pragma unroll
            for (int j = 0; j < 8; ++j) {
                v[j] = fmaxf(r.f[j], 0.f);
                cs[j] += v[j];
                cq[j] += v[j] * v[j];
            }
            *reinterpret_cast<float4*>(&g_h[(size_t)(b0 + mr + i) * FOC + c0]) =
                make_float4(v[0], v[1], v[2], v[3]);
            *reinterpret_cast<float4*>(&g_h[(size_t)(b0 + mr + i) * FOC + c0 + 4]) =
                make_float4(v[4], v[5], v[6], v[7]);
        }
#pragma unroll
        for (int j = 0; j < 8; ++j) {
            atomicAdd(&S.red[0][c0 + j], cs[j]);
            atomicAdd(&S.red[1][c0 + j], cq[j]);
        }
    }
    __syncthreads();
    if (tid < FOC) {
        atomicAdd(&g_stats[tid],       S.red[0][tid]);
        atomicAdd(&g_stats[FOC + tid], S.red[1][tid]);
    }
}

// ---------- BN + logits + softmax ----------
__global__ __launch_bounds__(256)
void head_kernel(const float* __restrict__ gamma, const float* __restrict__ beta,
                 const float* __restrict__ Wo2, const float* __restrict__ bo2,
                 float* __restrict__ out)
{
    __shared__ float s_scale[FOC];
    __shared__ float s_shift[FOC];
    __shared__ float s_w[FOC * 7];
    __shared__ float s_b[7];
    const int tid = threadIdx.x;

    if (tid < FOC) {
        const float inv = 1.0f / (float)BTOT;
        float mu  = g_stats[tid] * inv;
        float var = g_stats[FOC + tid] * inv - mu * mu;
        float sc  = gamma[tid] * rsqrtf(var + BN_EPS);
        s_scale[tid] = sc;
        s_shift[tid] = beta[tid] - mu * sc;
    }
    for (int i = tid; i < FOC * 7; i += 256) s_w[i] = Wo2[i];
    if (tid < 7) s_b[tid] = bo2[tid];
    __syncthreads();

    const int lane = tid & 31;
    const int warp = tid >> 5;
    const int row  = blockIdx.x * 8 + warp;

    float l[7] = {0, 0, 0, 0, 0, 0, 0};
#pragma unroll
    for (int ii = 0; ii < 8; ++ii) {
        const int c = lane + 32 * ii;
        const float v  = g_h[(size_t)row * FOC + c];
        const float hn = fmaf(v, s_scale[c], s_shift[c]);
#pragma unroll
        for (int j = 0; j < 7; ++j) l[j] = fmaf(hn, s_w[c * 7 + j], l[j]);
    }
#pragma unroll
    for (int off = 16; off > 0; off >>= 1) {
#pragma unroll
        for (int j = 0; j < 7; ++j) l[j] += __shfl_xor_sync(0xFFFFFFFFu, l[j], off);
    }
    if (lane == 0) {
        float m = -1e30f;
#pragma unroll
        for (int j = 0; j < 7; ++j) { l[j] += s_b[j]; m = fmaxf(m, l[j]); }
        float e[7], sum = 0.f;
#pragma unroll
        for (int j = 0; j < 7; ++j) { e[j] = expf(l[j] - m); sum += e[j]; }
        const float r = 1.0f / sum;
#pragma unroll
        for (int j = 0; j < 7; ++j) out[(size_t)row * 7 + j] = e[j] * r;
    }
}

extern "C" void kernel_launch(void* const* d_in, const int* in_sizes, int n_in,
                              void* d_out, int out_size)
{
    (void)in_sizes; (void)n_in; (void)out_size;
    const float* x    = (const float*)d_in[0];
    const float* W1   = (const float*)d_in[1];
    const float* b1   = (const float*)d_in[2];
    const float* W2   = (const float*)d_in[3];
    const float* b2   = (const float*)d_in[4];
    const float* W3   = (const float*)d_in[5];
    const float* b3   = (const float*)d_in[6];
    const float* Wo1  = (const float*)d_in[7];
    const float* bo1  = (const float*)d_in[8];
    const float* gam  = (const float*)d_in[9];
    const float* bet  = (const float*)d_in[10];
    const float* Wo2  = (const float*)d_in[11];
    const float* bo2  = (const float*)d_in[12];
    float* out = (float*)d_out;

    cudaFuncSetAttribute(rnn_kernel, cudaFuncAttributeMaxDynamicSharedMemorySize,
                         (int)sizeof(SmemLayout));

    zero_stats_kernel<<<2, 256>>>();
    rnn_kernel<<<NCTA, NTHR, sizeof(SmemLayout)>>>(x, W1, b1, W2, b2, W3, b3, Wo1, bo1);
    head_kernel<<<BTOT / 8, 256>>>(gam, bet, Wo2, bo2, out);
}

// round 9
// speedup vs baseline: 1.7889x; 1.7233x over previous
#include <cuda_runtime.h>
#include <math.h>

#define NODE   5
#define FML    64
#define F0C    256
#define F1C    256
#define FOC    256
#define TSTEPS 128
#define BTOT   8192
#define MROWS  64
#define NCTA   (BTOT / MROWS)   // 128
#define NTHR   256
#define BN_EPS 1e-5f
#define H2LD   260              // padded h2 row stride (floats)

// Scratch (static device arrays: allocation-free)
__device__ float g_h[BTOT * FOC];       // post-ReLU head activations (B,256)
__device__ float g_stats[2 * FOC];      // [0:256) sum, [256:512) sumsq

// parents as constexpr FUNCTIONS (usable in device code without
// --expt-relaxed-constexpr; fold to immediates under full unroll)
__device__ __host__ __forceinline__ constexpr int par0(int n) {
    return n == 0 ? 3 : n == 1 ? 0 : n == 2 ? 0 : n == 3 ? 1 : 2;
}
__device__ __host__ __forceinline__ constexpr int par1(int n) {
    return n == 0 ? 4 : n == 1 ? 4 : n == 2 ? 1 : n == 3 ? 2 : 3;
}

typedef unsigned long long u64;

struct Smem {
    float slot[6][MROWS][FML];   // 98304 B : rotating state arena (6 slots)
    float h1[MROWS][F0C];        // 65536 B : L1 output  (BN 'red' overlays this at head)
    float h2[MROWS][H2LD];       // 66560 B : L2 output, padded rows for L3 LDS
    float xs[NODE][MROWS];       //  1280 B
};                               // total 231680 B  (<= 227 KB)

__device__ __forceinline__ u64 dupf(float v) {
    u64 r;
    asm("mov.b64 %0, {%1, %1};" : "=l"(r) : "r"(__float_as_uint(v)));
    return r;
}
__device__ __forceinline__ void ffma2(u64& d, u64 a, u64 b) {
    asm("fma.rn.f32x2 %0, %1, %2, %0;" : "+l"(d) : "l"(a), "l"(b));
}

// One k4-iteration's worth of B: 4 k-rows x 8 cols = 8 ulonglong2
struct Bq { ulonglong2 q[8]; };

__device__ __forceinline__ Bq loadB(const float* __restrict__ B, int ldb) {
    Bq r;
#pragma unroll
    for (int kk = 0; kk < 4; ++kk) {
        r.q[2*kk]   = *reinterpret_cast<const ulonglong2*>(B + (size_t)kk * ldb);
        r.q[2*kk+1] = *reinterpret_cast<const ulonglong2*>(B + (size_t)kk * ldb + 4);
    }
    return r;
}

// acc[8 rows][8 cols packed] += A[8 rows][k4*4..+4] * B(4k x 8c)
__device__ __forceinline__ void macstep8(u64 (&acc)[8][4],
    const float* __restrict__ A, int lda, int k4, const Bq& b)
{
    float4 a[8];
#pragma unroll
    for (int r = 0; r < 8; ++r)
        a[r] = *reinterpret_cast<const float4*>(A + (size_t)r * lda + 4 * k4);
#pragma unroll
    for (int kk = 0; kk < 4; ++kk) {
        const u64 b0 = b.q[2*kk].x, b1 = b.q[2*kk].y;
        const u64 b2 = b.q[2*kk+1].x, b3 = b.q[2*kk+1].y;
#pragma unroll
        for (int r = 0; r < 8; ++r) {
            const float av4 = (kk == 0) ? a[r].x : (kk == 1) ? a[r].y
                            : (kk == 2) ? a[r].z : a[r].w;
            const u64 av = dupf(av4);
            ffma2(acc[r][0], av, b0); ffma2(acc[r][1], av, b1);
            ffma2(acc[r][2], av, b2); ffma2(acc[r][3], av, b3);
        }
    }
}

// double-buffered K-loop: B for iter k4+1 / k4+2 prefetched one macstep ahead
__device__ __forceinline__ void mac32x8(u64 (&acc)[8][4],
    const float* __restrict__ A, int lda,
    const float* __restrict__ B, int ldb, int K)
{
    const int K4 = K >> 2;   // always even here (16 or 64)
    Bq b0 = loadB(B, ldb);
#pragma unroll 1
    for (int k4 = 0; k4 < K4; k4 += 2) {
        Bq b1 = loadB(B + (size_t)4 * (k4 + 1) * ldb, ldb);
        macstep8(acc, A, lda, k4, b0);
        if (k4 + 2 < K4) b0 = loadB(B + (size_t)4 * (k4 + 2) * ldb, ldb);
        macstep8(acc, A, lda, k4 + 1, b1);
    }
}

// 2-row variant for layer 3
__device__ __forceinline__ void macstep2(u64 (&acc)[2][4],
    const float* __restrict__ A, int lda, int k4, const Bq& b)
{
    float4 a[2];
    a[0] = *reinterpret_cast<const float4*>(A + 4 * k4);
    a[1] = *reinterpret_cast<const float4*>(A + lda + 4 * k4);
#pragma unroll
    for (int kk = 0; kk < 4; ++kk) {
        const u64 b0 = b.q[2*kk].x, b1 = b.q[2*kk].y;
        const u64 b2 = b.q[2*kk+1].x, b3 = b.q[2*kk+1].y;
#pragma unroll
        for (int r = 0; r < 2; ++r) {
            const float av4 = (kk == 0) ? a[r].x : (kk == 1) ? a[r].y
                            : (kk == 2) ? a[r].z : a[r].w;
            const u64 av = dupf(av4);
            ffma2(acc[r][0], av, b0); ffma2(acc[r][1], av, b1);
            ffma2(acc[r][2], av, b2); ffma2(acc[r][3], av, b3);
        }
    }
}

__device__ __forceinline__ void mac32x2(u64 (&acc)[2][4],
    const float* __restrict__ A, int lda,
    const float* __restrict__ B, int ldb, int K)
{
    const int K4 = K >> 2;
    Bq b0 = loadB(B, ldb);
#pragma unroll 1
    for (int k4 = 0; k4 < K4; k4 += 2) {
        Bq b1 = loadB(B + (size_t)4 * (k4 + 1) * ldb, ldb);
        macstep2(acc, A, lda, k4, b0);
        if (k4 + 2 < K4) b0 = loadB(B + (size_t)4 * (k4 + 2) * ldb, ldb);
        macstep2(acc, A, lda, k4 + 1, b1);
    }
}

__global__ void zero_stats_kernel()
{
    int i = blockIdx.x * blockDim.x + threadIdx.x;
    if (i < 2 * FOC) g_stats[i] = 0.0f;
}

__global__ __launch_bounds__(NTHR, 1)
void rnn_kernel(const float* __restrict__ x,
                const float* __restrict__ W1, const float* __restrict__ b1,
                const float* __restrict__ W2, const float* __restrict__ b2,
                const float* __restrict__ W3, const float* __restrict__ b3,
                const float* __restrict__ Wo1, const float* __restrict__ bo1)
{
    extern __shared__ char smem_raw[];
    Smem& S = *reinterpret_cast<Smem*>(smem_raw);
    const int tid = threadIdx.x;
    const int tx  = tid & 31;
    const int w   = tid >> 5;         // warp 0..7 -> column slice
    const int cg  = tx & 3;           // col group within warp
    const int rg  = tx >> 2;          // row group
    const int r0  = rg * 8;           // lane's 8 rows
    const int c0  = w * 32 + cg * 8;  // lane's 8 cols (L1/L2/head)
    const int c3  = w * 8;            // L3: warp's 8 cols
    const int lr  = tx * 2;           // L3: lane's 2 rows
    const int b0  = blockIdx.x * MROWS;

    // zero the state arena
    for (int i = tid; i < 6 * MROWS * FML; i += NTHR)
        (&S.slot[0][0][0])[i] = 0.0f;
    __syncthreads();

    // slot map: sl[0..4] = physical slot of logical node state, sl[5] = spare
    int sl[6] = {0, 1, 2, 3, 4, 5};

    for (int t = 0; t < TSTEPS; ++t) {
        for (int i = tid; i < NODE * MROWS; i += NTHR) {
            const int n = i >> 6, r = i & 63;
            S.xs[n][r] = x[(size_t)(b0 + r) * (NODE * TSTEPS) + n * TSTEPS + t];
        }
        __syncthreads();

#pragma unroll
        for (int n = 0; n < NODE; ++n) {
            const int p0 = par0(n), p1 = par1(n);
            const float* W1n = W1 + (size_t)n * (2 + 2 * FML) * F0C;
            const float* sp0 = &S.slot[sl[p0]][0][0];
            const float* sp1 = &S.slot[sl[p1]][0][0];

            // ---------- Layer 1: inp(130) -> 256, ReLU ----------
            u64 acc[8][4];
            {
                const ulonglong2 bb0 = *(const ulonglong2*)(b1 + n * F0C + c0);
                const ulonglong2 bb1 = *(const ulonglong2*)(b1 + n * F0C + c0 + 4);
                const ulonglong2 wa0 = *(const ulonglong2*)(W1n + c0);
                const ulonglong2 wa1 = *(const ulonglong2*)(W1n + c0 + 4);
                const ulonglong2 wb0 = *(const ulonglong2*)(W1n + F0C + c0);
                const ulonglong2 wb1 = *(const ulonglong2*)(W1n + F0C + c0 + 4);
#pragma unroll
                for (int r = 0; r < 8; ++r) {
                    const u64 xa = dupf(S.xs[p0][r0 + r]);
                    const u64 xb = dupf(S.xs[p1][r0 + r]);
                    acc[r][0] = bb0.x; acc[r][1] = bb0.y;
                    acc[r][2] = bb1.x; acc[r][3] = bb1.y;
                    ffma2(acc[r][0], xa, wa0.x); ffma2(acc[r][1], xa, wa0.y);
                    ffma2(acc[r][2], xa, wa1.x); ffma2(acc[r][3], xa, wa1.y);
                    ffma2(acc[r][0], xb, wb0.x); ffma2(acc[r][1], xb, wb0.y);
                    ffma2(acc[r][2], xb, wb1.x); ffma2(acc[r][3], xb, wb1.y);
                }
            }
            mac32x8(acc, sp0 + (size_t)r0 * FML, FML, W1n + 2 * F0C + c0, F0C, FML);
            mac32x8(acc, sp1 + (size_t)r0 * FML, FML, W1n + (size_t)(2 + FML) * F0C + c0, F0C, FML);
#pragma unroll
            for (int r = 0; r < 8; ++r) {
                union { u64 u[4]; float f[8]; } v;
                v.u[0] = acc[r][0]; v.u[1] = acc[r][1];
                v.u[2] = acc[r][2]; v.u[3] = acc[r][3];
                *(float4*)&S.h1[r0 + r][c0] =
                    make_float4(fmaxf(v.f[0], 0.f), fmaxf(v.f[1], 0.f),
                                fmaxf(v.f[2], 0.f), fmaxf(v.f[3], 0.f));
                *(float4*)&S.h1[r0 + r][c0 + 4] =
                    make_float4(fmaxf(v.f[4], 0.f), fmaxf(v.f[5], 0.f),
                                fmaxf(v.f[6], 0.f), fmaxf(v.f[7], 0.f));
            }
            __syncthreads();

            // ---------- Layer 2: 256 -> 256, ReLU ----------
            const float* W2n = W2 + (size_t)n * F0C * F1C;
            {
                const ulonglong2 bb0 = *(const ulonglong2*)(b2 + n * F1C + c0);
                const ulonglong2 bb1 = *(const ulonglong2*)(b2 + n * F1C + c0 + 4);
#pragma unroll
                for (int r = 0; r < 8; ++r) {
                    acc[r][0] = bb0.x; acc[r][1] = bb0.y;
                    acc[r][2] = bb1.x; acc[r][3] = bb1.y;
                }
            }
            mac32x8(acc, &S.h1[r0][0], F0C, W2n + c0, F1C, F0C);
#pragma unroll
            for (int r = 0; r < 8; ++r) {
                union { u64 u[4]; float f[8]; } v;
                v.u[0] = acc[r][0]; v.u[1] = acc[r][1];
                v.u[2] = acc[r][2]; v.u[3] = acc[r][3];
                *(float4*)&S.h2[r0 + r][c0] =
                    make_float4(fmaxf(v.f[0], 0.f), fmaxf(v.f[1], 0.f),
                                fmaxf(v.f[2], 0.f), fmaxf(v.f[3], 0.f));
                *(float4*)&S.h2[r0 + r][c0 + 4] =
                    make_float4(fmaxf(v.f[4], 0.f), fmaxf(v.f[5], 0.f),
                                fmaxf(v.f[6], 0.f), fmaxf(v.f[7], 0.f));
            }
            __syncthreads();

            // ---------- Layer 3: 256 -> 64, tanh -> state slot ----------
            {
                const float* W3n = W3 + (size_t)n * F1C * FML;
                const int ds = (n == 0) ? sl[5] : (n == 1) ? sl[4] : sl[n - 2];
                float* dst = &S.slot[ds][0][0];
                u64 a2[2][4];
                {
                    const ulonglong2 bb0 = *(const ulonglong2*)(b3 + n * FML + c3);
                    const ulonglong2 bb1 = *(const ulonglong2*)(b3 + n * FML + c3 + 4);
                    a2[0][0] = bb0.x; a2[0][1] = bb0.y; a2[0][2] = bb1.x; a2[0][3] = bb1.y;
                    a2[1][0] = bb0.x; a2[1][1] = bb0.y; a2[1][2] = bb1.x; a2[1][3] = bb1.y;
                }
                mac32x2(a2, &S.h2[lr][0], H2LD, W3n + c3, FML, F1C);
#pragma unroll
                for (int r = 0; r < 2; ++r) {
                    union { u64 u[4]; float f[8]; } v;
                    v.u[0] = a2[r][0]; v.u[1] = a2[r][1];
                    v.u[2] = a2[r][2]; v.u[3] = a2[r][3];
                    *(float4*)&dst[(size_t)(lr + r) * FML + c3] =
                        make_float4(tanhf(v.f[0]), tanhf(v.f[1]),
                                    tanhf(v.f[2]), tanhf(v.f[3]));
                    *(float4*)&dst[(size_t)(lr + r) * FML + c3 + 4] =
                        make_float4(tanhf(v.f[4]), tanhf(v.f[5]),
                                    tanhf(v.f[6]), tanhf(v.f[7]));
                }
            }
            __syncthreads();
        }

        // rotate slot map: new0->old spare, new1->old sl4, new2->old sl0,
        // new3->old sl1, new4->old sl2, spare->old sl3
        {
            const int t0 = sl[0], t1 = sl[1], t2 = sl[2];
            const int t3 = sl[3], t4 = sl[4], t5 = sl[5];
            sl[0] = t5; sl[1] = t4; sl[2] = t0;
            sl[3] = t1; sl[4] = t2; sl[5] = t3;
        }
    }

    // ---------- Head GEMM: feat(325) @ Wo1 -> ReLU -> g_h + BN partials ----------
    float* red = &S.h1[0][0];   // h1 is free now; reuse as reduction buffer
    for (int i = tid; i < 2 * FOC; i += NTHR) red[i] = 0.0f;
    __syncthreads();

    {
        u64 acc[8][4];
        {
            const ulonglong2 bb0 = *(const ulonglong2*)(bo1 + c0);
            const ulonglong2 bb1 = *(const ulonglong2*)(bo1 + c0 + 4);
#pragma unroll
            for (int r = 0; r < 8; ++r) {
                acc[r][0] = bb0.x; acc[r][1] = bb0.y;
                acc[r][2] = bb1.x; acc[r][3] = bb1.y;
            }
        }
#pragma unroll
        for (int n = 0; n < NODE; ++n) {   // x part (rows 0..4 of Wo1); xs holds t=T-1
            const ulonglong2 w0 = *(const ulonglong2*)(Wo1 + n * FOC + c0);
            const ulonglong2 w1 = *(const ulonglong2*)(Wo1 + n * FOC + c0 + 4);
#pragma unroll
            for (int r = 0; r < 8; ++r) {
                const u64 xv = dupf(S.xs[n][r0 + r]);
                ffma2(acc[r][0], xv, w0.x); ffma2(acc[r][1], xv, w0.y);
                ffma2(acc[r][2], xv, w1.x); ffma2(acc[r][3], xv, w1.y);
            }
        }
#pragma unroll
        for (int n = 0; n < NODE; ++n) {   // state part (rows 5 + n*64 + f)
            mac32x8(acc, &S.slot[sl[n]][r0][0], FML,
                    Wo1 + (size_t)(NODE + n * FML) * FOC + c0, FOC, FML);
        }
        float cs[8] = {0,0,0,0,0,0,0,0};
        float cq[8] = {0,0,0,0,0,0,0,0};
#pragma unroll
        for (int r = 0; r < 8; ++r) {
            union { u64 u[4]; float f[8]; } v;
            v.u[0] = acc[r][0]; v.u[1] = acc[r][1];
            v.u[2] = acc[r][2]; v.u[3] = acc[r][3];
            float vv[8];
#pragma unroll
            for (int j = 0; j < 8; ++j) {
                vv[j] = fmaxf(v.f[j], 0.f);
                cs[j] += vv[j];
                cq[j] += vv[j] * vv[j];
            }
            *(float4*)&g_h[(size_t)(b0 + r0 + r) * FOC + c0] =
                make_float4(vv[0], vv[1], vv[2], vv[3]);
            *(float4*)&g_h[(size_t)(b0 + r0 + r) * FOC + c0 + 4] =
                make_float4(vv[4], vv[5], vv[6], vv[7]);
        }
#pragma unroll
        for (int j = 0; j < 8; ++j) {
            atomicAdd(&red[c0 + j],       cs[j]);
            atomicAdd(&red[FOC + c0 + j], cq[j]);
        }
    }
    __syncthreads();
    if (tid < FOC) {
        atomicAdd(&g_stats[tid],       red[tid]);
        atomicAdd(&g_stats[FOC + tid], red[FOC + tid]);
    }
}

// ---------- BN + logits + softmax ----------
__global__ __launch_bounds__(256)
void head_kernel(const float* __restrict__ gamma, const float* __restrict__ beta,
                 const float* __restrict__ Wo2, const float* __restrict__ bo2,
                 float* __restrict__ out)
{
    __shared__ float s_scale[FOC];
    __shared__ float s_shift[FOC];
    __shared__ float s_w[FOC * 7];
    __shared__ float s_b[7];
    const int tid = threadIdx.x;

    if (tid < FOC) {
        const float inv = 1.0f / (float)BTOT;
        float mu  = g_stats[tid] * inv;
        float var = g_stats[FOC + tid] * inv - mu * mu;
        float sc  = gamma[tid] * rsqrtf(var + BN_EPS);
        s_scale[tid] = sc;
        s_shift[tid] = beta[tid] - mu * sc;
    }
    for (int i = tid; i < FOC * 7; i += 256) s_w[i] = Wo2[i];
    if (tid < 7) s_b[tid] = bo2[tid];
    __syncthreads();

    const int lane = tid & 31;
    const int warp = tid >> 5;
    const int row  = blockIdx.x * 8 + warp;

    float l[7] = {0, 0, 0, 0, 0, 0, 0};
#pragma unroll
    for (int ii = 0; ii < 8; ++ii) {
        const int c = lane + 32 * ii;
        const float v  = g_h[(size_t)row * FOC + c];
        const float hn = fmaf(v, s_scale[c], s_shift[c]);
#pragma unroll
        for (int j = 0; j < 7; ++j) l[j] = fmaf(hn, s_w[c * 7 + j], l[j]);
    }
#pragma unroll
    for (int off = 16; off > 0; off >>= 1) {
#pragma unroll
        for (int j = 0; j < 7; ++j) l[j] += __shfl_xor_sync(0xFFFFFFFFu, l[j], off);
    }
    if (lane == 0) {
        float m = -1e30f;
#pragma unroll
        for (int j = 0; j < 7; ++j) { l[j] += s_b[j]; m = fmaxf(m, l[j]); }
        float e[7], sum = 0.f;
#pragma unroll
        for (int j = 0; j < 7; ++j) { e[j] = expf(l[j] - m); sum += e[j]; }
        const float r = 1.0f / sum;
#pragma unroll
        for (int j = 0; j < 7; ++j) out[(size_t)row * 7 + j] = e[j] * r;
    }
}

extern "C" void kernel_launch(void* const* d_in, const int* in_sizes, int n_in,
                              void* d_out, int out_size)
{
    (void)in_sizes; (void)n_in; (void)out_size;
    const float* x    = (const float*)d_in[0];
    const float* W1   = (const float*)d_in[1];
    const float* b1   = (const float*)d_in[2];
    const float* W2   = (const float*)d_in[3];
    const float* b2   = (const float*)d_in[4];
    const float* W3   = (const float*)d_in[5];
    const float* b3   = (const float*)d_in[6];
    const float* Wo1  = (const float*)d_in[7];
    const float* bo1  = (const float*)d_in[8];
    const float* gam  = (const float*)d_in[9];
    const float* bet  = (const float*)d_in[10];
    const float* Wo2  = (const float*)d_in[11];
    const float* bo2  = (const float*)d_in[12];
    float* out = (float*)d_out;

    cudaFuncSetAttribute(rnn_kernel, cudaFuncAttributeMaxDynamicSharedMemorySize,
                         (int)sizeof(Smem));

    zero_stats_kernel<<<2, 256>>>();
    rnn_kernel<<<NCTA, NTHR, sizeof(Smem)>>>(x, W1, b1, W2, b2, W3, b3, Wo1, bo1);
    head_kernel<<<BTOT / 8, 256>>>(gam, bet, Wo2, bo2, out);
}